// round 1
// baseline (speedup 1.0000x reference)
#include <cuda_runtime.h>
#include <math.h>

#define BB   8
#define LL   512
#define BL   4096      // B*L
#define DM   768
#define DI   1536
#define NS   16
#define DTR  48
#define KSP  7
#define DCV  4

// ---------------- scratch (device globals; no allocation allowed) ----------
__device__ float g_xn[BL * DM];
__device__ float g_xgcn[BL * DM];
__device__ float g_xz[BL * 2 * DI];
__device__ float g_xmc[BL * DI];
__device__ float g_xdbl[BL * 80];
__device__ float g_dtb[BL * DI];
__device__ float g_y[BL * DI];
__device__ float g_xmamba[BL * DM];
__device__ float g_gbuf[BL * DM];
__device__ float g_fused[BL * DM];
__device__ float g_tmp[BL * DM];
__device__ float g_wconvt[KSP * DM * DM];   // (k*DM+i, o)

// ---------------- generic tiled SGEMM: C[M,N] (+)= A[M,K]@B[K,N] ----------
constexpr int TBM = 64, TBN = 64, TBK = 16;

template<bool ACCUM, bool BIAS, int ACT>   // ACT: 0=none, 1=softplus
__global__ __launch_bounds__(256) void sgemm_k(
    const float* __restrict__ A, int lda,
    const float* __restrict__ B,
    const float* __restrict__ bias,
    float* __restrict__ C, int ldc,
    int N, int K)
{
    __shared__ float As[TBK][TBM + 4];
    __shared__ float Bs[TBK][TBN];
    const int tid = threadIdx.x;
    const int bm = blockIdx.y * TBM;
    const int bn = blockIdx.x * TBN;
    const int tx = tid & 15, ty = tid >> 4;
    const int aRow = tid >> 2, aCol = (tid & 3) << 2;
    const int bRow = tid >> 4, bCol = (tid & 15) << 2;

    float acc[4][4] = {};

    for (int k0 = 0; k0 < K; k0 += TBK) {
        // load A tile (64x16) transposed into smem
        {
            float4 va = *(const float4*)(A + (size_t)(bm + aRow) * lda + k0 + aCol);
            As[aCol + 0][aRow] = va.x;
            As[aCol + 1][aRow] = va.y;
            As[aCol + 2][aRow] = va.z;
            As[aCol + 3][aRow] = va.w;
        }
        // load B tile (16x64)
        {
            int c = bn + bCol;
            const float* bp = B + (size_t)(k0 + bRow) * N + c;
            float4 vb;
            if (c + 3 < N) {
                vb = *(const float4*)bp;
            } else {
                vb.x = (c + 0 < N) ? bp[0] : 0.f;
                vb.y = (c + 1 < N) ? bp[1] : 0.f;
                vb.z = (c + 2 < N) ? bp[2] : 0.f;
                vb.w = (c + 3 < N) ? bp[3] : 0.f;
            }
            *(float4*)&Bs[bRow][bCol] = vb;
        }
        __syncthreads();
        #pragma unroll
        for (int k = 0; k < TBK; k++) {
            float4 a4 = *(const float4*)&As[k][ty << 2];
            float4 b4 = *(const float4*)&Bs[k][tx << 2];
            float a[4] = {a4.x, a4.y, a4.z, a4.w};
            float b[4] = {b4.x, b4.y, b4.z, b4.w};
            #pragma unroll
            for (int i = 0; i < 4; i++)
                #pragma unroll
                for (int j = 0; j < 4; j++)
                    acc[i][j] = fmaf(a[i], b[j], acc[i][j]);
        }
        __syncthreads();
    }

    #pragma unroll
    for (int i = 0; i < 4; i++) {
        int r = bm + (ty << 2) + i;
        #pragma unroll
        for (int j = 0; j < 4; j++) {
            int cc = bn + (tx << 2) + j;
            if (cc < N) {
                float v = acc[i][j];
                if (BIAS)  v += bias[cc];
                if (ACCUM) v += C[(size_t)r * ldc + cc];
                if (ACT == 1) v = (v > 20.f) ? v : log1pf(__expf(v));
                C[(size_t)r * ldc + cc] = v;
            }
        }
    }
}

// -------- conv-as-GEMM: x_gcn += shifted(xn) @ wconvt + conv_b ------------
__global__ __launch_bounds__(256) void conv_sgemm_k(const float* __restrict__ bias)
{
    const int N = DM, K = KSP * DM;
    __shared__ float As[TBK][TBM + 4];
    __shared__ float Bs[TBK][TBN];
    const int tid = threadIdx.x;
    const int bm = blockIdx.y * TBM;
    const int bn = blockIdx.x * TBN;
    const int tx = tid & 15, ty = tid >> 4;
    const int aRow = tid >> 2, aCol = (tid & 3) << 2;
    const int bRow = tid >> 4, bCol = (tid & 15) << 2;

    const int r = bm + aRow;
    const int bb = r >> 9;
    const int l = r & 511;

    float acc[4][4] = {};

    for (int k0 = 0; k0 < K; k0 += TBK) {
        {
            int kk = k0 + aCol;
            int tap = kk / DM;
            int ii = kk - tap * DM;
            int ls = l + tap - 3;
            float4 va = make_float4(0.f, 0.f, 0.f, 0.f);
            if (ls >= 0 && ls < LL)
                va = *(const float4*)(g_xn + ((size_t)(bb * LL + ls)) * DM + ii);
            As[aCol + 0][aRow] = va.x;
            As[aCol + 1][aRow] = va.y;
            As[aCol + 2][aRow] = va.z;
            As[aCol + 3][aRow] = va.w;
        }
        {
            float4 vb = *(const float4*)(g_wconvt + (size_t)(k0 + bRow) * N + bn + bCol);
            *(float4*)&Bs[bRow][bCol] = vb;
        }
        __syncthreads();
        #pragma unroll
        for (int k = 0; k < TBK; k++) {
            float4 a4 = *(const float4*)&As[k][ty << 2];
            float4 b4 = *(const float4*)&Bs[k][tx << 2];
            float a[4] = {a4.x, a4.y, a4.z, a4.w};
            float b[4] = {b4.x, b4.y, b4.z, b4.w};
            #pragma unroll
            for (int i = 0; i < 4; i++)
                #pragma unroll
                for (int j = 0; j < 4; j++)
                    acc[i][j] = fmaf(a[i], b[j], acc[i][j]);
        }
        __syncthreads();
    }

    #pragma unroll
    for (int i = 0; i < 4; i++) {
        int rr = bm + (ty << 2) + i;
        #pragma unroll
        for (int j = 0; j < 4; j++) {
            int cc = bn + (tx << 2) + j;
            float* cp = g_xgcn + (size_t)rr * DM + cc;
            *cp = *cp + acc[i][j] + bias[cc];
        }
    }
}

// ---------------- conv weight transpose: (o,i,k) -> (k*DM+i, o) -----------
__global__ void convw_t_k(const float* __restrict__ cw)
{
    int idx = blockIdx.x * blockDim.x + threadIdx.x;
    if (idx >= KSP * DM * DM) return;
    int o = idx % DM;
    int t = idx / DM;
    int i = t % DM;
    int k = t / DM;
    g_wconvt[idx] = cw[(o * DM + i) * KSP + k];
}

// ---------------- layernorm (optionally + residual) -----------------------
__global__ __launch_bounds__(256) void ln_k(
    const float* __restrict__ x, const float* __restrict__ res,
    const float* __restrict__ w, const float* __restrict__ b,
    float* __restrict__ out)
{
    int row = blockIdx.x;
    const float* xr = x + (size_t)row * DM;
    float v[3];
    float s = 0.f, s2 = 0.f;
    #pragma unroll
    for (int i = 0; i < 3; i++) {
        int c = threadIdx.x + i * 256;
        float t = xr[c];
        if (res) t += res[(size_t)row * DM + c];
        v[i] = t; s += t; s2 += t * t;
    }
    int lane = threadIdx.x & 31, wid = threadIdx.x >> 5;
    #pragma unroll
    for (int o = 16; o >= 1; o >>= 1) {
        s  += __shfl_xor_sync(0xffffffffu, s,  o);
        s2 += __shfl_xor_sync(0xffffffffu, s2, o);
    }
    __shared__ float sa[8], sb[8];
    if (lane == 0) { sa[wid] = s; sb[wid] = s2; }
    __syncthreads();
    if (wid == 0) {
        s  = (lane < 8) ? sa[lane] : 0.f;
        s2 = (lane < 8) ? sb[lane] : 0.f;
        #pragma unroll
        for (int o = 4; o >= 1; o >>= 1) {
            s  += __shfl_xor_sync(0xffffffffu, s,  o);
            s2 += __shfl_xor_sync(0xffffffffu, s2, o);
        }
        if (lane == 0) { sa[0] = s; sb[0] = s2; }
    }
    __syncthreads();
    float mean = sa[0] * (1.f / DM);
    float var  = sb[0] * (1.f / DM) - mean * mean;
    float rstd = rsqrtf(var + 1e-5f);
    #pragma unroll
    for (int i = 0; i < 3; i++) {
        int c = threadIdx.x + i * 256;
        out[(size_t)row * DM + c] = (v[i] - mean) * rstd * w[c] + b[c];
    }
}

// ---------------- depthwise causal conv + bias + silu ---------------------
__global__ void dwconv_k(const float* __restrict__ w, const float* __restrict__ bias)
{
    int idx = blockIdx.x * blockDim.x + threadIdx.x;
    if (idx >= BL * DI) return;
    int d = idx % DI;
    int row = idx / DI;
    int l = row & 511, bb = row >> 9;
    float s = bias[d];
    #pragma unroll
    for (int j = 0; j < DCV; j++) {
        int ls = l - 3 + j;
        if (ls >= 0)
            s += g_xz[((size_t)(bb * LL + ls)) * 2 * DI + d] * w[d * DCV + j];
    }
    float sg = 1.f / (1.f + __expf(-s));
    g_xmc[idx] = s * sg;
}

// ---------------- selective scan ------------------------------------------
// grid (DI/16, B), 256 threads; each 16-lane group owns one (b,d) chain,
// lane = state index n. Fuses +D*x and *silu(z) epilogue.
__global__ __launch_bounds__(256) void scan_k(
    const float* __restrict__ A_log, const float* __restrict__ Dvec)
{
    int tid = threadIdx.x;
    int n = tid & 15;
    int d = blockIdx.x * 16 + (tid >> 4);
    int b = blockIdx.y;
    float A = -__expf(A_log[d * NS + n]);
    float Dd = Dvec[d];
    float h = 0.f;
    const float* dtp = g_dtb  + (size_t)b * LL * DI + d;
    const float* xp  = g_xmc  + (size_t)b * LL * DI + d;
    const float* zp  = g_xz   + (size_t)b * LL * 2 * DI + DI + d;
    const float* dbl = g_xdbl + (size_t)b * LL * 80;
    float* yp        = g_y    + (size_t)b * LL * DI + d;
    for (int l = 0; l < LL; l++) {
        float dtv = dtp[(size_t)l * DI];
        float xv  = xp[(size_t)l * DI];
        float Bn  = dbl[l * 80 + 48 + n];
        float Cn  = dbl[l * 80 + 64 + n];
        h = __expf(dtv * A) * h + dtv * Bn * xv;
        float p = h * Cn;
        #pragma unroll
        for (int o = 8; o >= 1; o >>= 1)
            p += __shfl_xor_sync(0xffffffffu, p, o, 16);
        if (n == 0) {
            float zv = zp[(size_t)l * 2 * DI];
            float sz = zv / (1.f + __expf(-zv));
            yp[(size_t)l * DI] = (p + Dd * xv) * sz;
        }
    }
}

// ---------------- gate fusion ---------------------------------------------
__global__ void fuse_k()
{
    int idx = blockIdx.x * blockDim.x + threadIdx.x;
    if (idx >= BL * DM) return;
    float g = 1.f / (1.f + __expf(-g_gbuf[idx]));
    g_fused[idx] = g * g_xgcn[idx] + (1.f - g) * g_xmamba[idx];
}

// ---------------- adjacency ------------------------------------------------
__global__ void adj_k(const float* __restrict__ nv1, const float* __restrict__ nv2,
                      float* __restrict__ out)
{
    int idx = blockIdx.x * blockDim.x + threadIdx.x;
    if (idx >= 64 * 64) return;
    int i = idx >> 6, j = idx & 63;
    float s = 0.f;
    #pragma unroll
    for (int k = 0; k < 16; k++) s += nv1[i * 16 + k] * nv2[k * 64 + j];
    float a = 1.f / (1.f + __expf(-s));
    out[idx] = (i == j) ? 0.f : a;
}

// ---------------- host launch ---------------------------------------------
extern "C" void kernel_launch(void* const* d_in, const int* in_sizes, int n_in,
                              void* d_out, int out_size)
{
    const float* x        = (const float*)d_in[0];
    const float* nv1      = (const float*)d_in[1];
    const float* nv2      = (const float*)d_in[2];
    const float* norm1_w  = (const float*)d_in[3];
    const float* norm1_b  = (const float*)d_in[4];
    const float* norm2_w  = (const float*)d_in[5];
    const float* norm2_b  = (const float*)d_in[6];
    const float* gcn_w    = (const float*)d_in[7];
    const float* gcn_b    = (const float*)d_in[8];
    const float* conv_w   = (const float*)d_in[9];
    const float* conv_b   = (const float*)d_in[10];
    const float* gg_w     = (const float*)d_in[11];
    const float* gg_b     = (const float*)d_in[12];
    const float* gm_w     = (const float*)d_in[13];
    const float* gm_b     = (const float*)d_in[14];
    const float* out_w    = (const float*)d_in[15];
    const float* out_b    = (const float*)d_in[16];
    const float* m_in_w   = (const float*)d_in[17];
    const float* m_conv_w = (const float*)d_in[18];
    const float* m_conv_b = (const float*)d_in[19];
    const float* m_xproj_w= (const float*)d_in[20];
    const float* m_dt_w   = (const float*)d_in[21];
    const float* m_dt_b   = (const float*)d_in[22];
    const float* m_A_log  = (const float*)d_in[23];
    const float* m_D      = (const float*)d_in[24];
    const float* m_out_w  = (const float*)d_in[25];
    float* out = (float*)d_out;

    float *xn, *xgcn, *xz, *xmc, *xdbl, *dtb, *y, *xmamba, *gbuf, *fused, *tmp;
    cudaGetSymbolAddress((void**)&xn,    g_xn);
    cudaGetSymbolAddress((void**)&xgcn,  g_xgcn);
    cudaGetSymbolAddress((void**)&xz,    g_xz);
    cudaGetSymbolAddress((void**)&xmc,   g_xmc);
    cudaGetSymbolAddress((void**)&xdbl,  g_xdbl);
    cudaGetSymbolAddress((void**)&dtb,   g_dtb);
    cudaGetSymbolAddress((void**)&y,     g_y);
    cudaGetSymbolAddress((void**)&xmamba,g_xmamba);
    cudaGetSymbolAddress((void**)&gbuf,  g_gbuf);
    cudaGetSymbolAddress((void**)&fused, g_fused);
    cudaGetSymbolAddress((void**)&tmp,   g_tmp);

    // adjacency output (second tuple element)
    adj_k<<<16, 256>>>(nv1, nv2, out + (size_t)BL * DM);

    // conv weight transpose (cheap, re-done every call for determinism)
    convw_t_k<<<(KSP * DM * DM + 255) / 256, 256>>>(conv_w);

    // xn = LN1(x)
    ln_k<<<BL, 256>>>(x, nullptr, norm1_w, norm1_b, xn);

    const dim3 gDM(DM / TBN, BL / TBM);

    // x_gcn = xn @ gcn_w + gcn_b
    sgemm_k<false, true, 0><<<gDM, 256>>>(xn, DM, gcn_w, gcn_b, xgcn, DM, DM, DM);
    // x_gcn += dense conv over L (+conv_b)
    conv_sgemm_k<<<gDM, 256>>>(conv_b);

    // mamba in_proj: xz = xn @ m_in_w   (N = 3072)
    sgemm_k<false, false, 0><<<dim3(2 * DI / TBN, BL / TBM), 256>>>(
        xn, DM, m_in_w, nullptr, xz, 2 * DI, 2 * DI, DM);

    // depthwise causal conv + bias + silu -> xmc
    dwconv_k<<<(BL * DI + 255) / 256, 256>>>(m_conv_w, m_conv_b);

    // x_dbl = xmc @ m_xproj_w  (N = 80)
    sgemm_k<false, false, 0><<<dim3(2, BL / TBM), 256>>>(
        xmc, DI, m_xproj_w, nullptr, xdbl, 80, 80, DI);

    // dt = softplus(x_dbl[:, :48] @ m_dt_w + m_dt_b)
    sgemm_k<false, true, 1><<<dim3(DI / TBN, BL / TBM), 256>>>(
        xdbl, 80, m_dt_w, m_dt_b, dtb, DI, DI, DTR);

    // selective scan (+D*x, *silu(z) fused)
    scan_k<<<dim3(DI / 16, BB), 256>>>(m_A_log, m_D);

    // x_mamba = y @ m_out_w
    sgemm_k<false, false, 0><<<gDM, 256>>>(y, DI, m_out_w, nullptr, xmamba, DM, DM, DI);

    // gate = sigmoid(x_gcn@Wg1+b1 + x_mamba@Wg2+b2); fused = g*x_gcn+(1-g)*x_mamba
    sgemm_k<false, true, 0><<<gDM, 256>>>(xgcn, DM, gg_w, gg_b, gbuf, DM, DM, DM);
    sgemm_k<true,  true, 0><<<gDM, 256>>>(xmamba, DM, gm_w, gm_b, gbuf, DM, DM, DM);
    fuse_k<<<(BL * DM + 255) / 256, 256>>>();

    // out = LN2(fused @ out_w + out_b + x)
    sgemm_k<false, true, 0><<<gDM, 256>>>(fused, DM, out_w, out_b, tmp, DM, DM, DM);
    ln_k<<<BL, 256>>>(tmp, x, norm2_w, norm2_b, out);
}